// round 6
// baseline (speedup 1.0000x reference)
#include <cuda_runtime.h>

typedef unsigned long long ull;

#define BB 8
#define LL 4096
#define DX 128
#define BL (BB*LL)
#define NS 132   // padded smem row stride (floats) — conflict-free strided LDS

// ---------------- scratch ----------------
__device__ float g_v1[DX], g_u1[DX], g_u2[DX];
__device__ float g_cq[BB];
__device__ float g_cconst;
__device__ float g_logits[BL], g_d1[BL], g_d2[BL];
__device__ float g_si[BL], g_sjc[BL];
__device__ float g_invZ[BL];
__device__ float g_Zpart[BL*4], g_Spart[BL*4];
__device__ float g_Mpart[BB*8*10], g_Fpart[BB*8*10];
__device__ float g_psum[BB*8];
__device__ unsigned g_lmax[BB];
__device__ unsigned g_msi, g_msjc;

// ---------------- exp(sigmoid(t)) Taylor deg-9, valid |t|<=1 ----------------
#define P0f  1.64872127f
#define P1f  0.412180318f
#define P2f  0.0515225397f
#define P3f (-0.03005490f)
#define P4f (-0.00831874f)
#define P5f  0.00237489f
#define P6f  0.00112763f
#define P7f (-1.56355e-4f)
#define P8f (-1.38606e-4f)
#define P9f  5.4551e-6f

__constant__ float c_P[10] = {P0f,P1f,P2f,P3f,P4f,P5f,P6f,P7f,P8f,P9f};
__constant__ float c_BIN[10][10] = {
    {1,0,0,0,0,0,0,0,0,0},
    {1,1,0,0,0,0,0,0,0,0},
    {1,2,1,0,0,0,0,0,0,0},
    {1,3,3,1,0,0,0,0,0,0},
    {1,4,6,4,1,0,0,0,0,0},
    {1,5,10,10,5,1,0,0,0,0},
    {1,6,15,20,15,6,1,0,0,0},
    {1,7,21,35,35,21,7,1,0,0},
    {1,8,28,56,70,56,28,8,1,0},
    {1,9,36,84,126,126,84,36,9,1},
};

__device__ __forceinline__ float fpoly(float t){
    float r = P9f;
    r = fmaf(r,t,P8f); r = fmaf(r,t,P7f); r = fmaf(r,t,P6f);
    r = fmaf(r,t,P5f); r = fmaf(r,t,P4f); r = fmaf(r,t,P3f);
    r = fmaf(r,t,P2f); r = fmaf(r,t,P1f); r = fmaf(r,t,P0f);
    return r;
}

__device__ __forceinline__ float ex2a(float x){ float r; asm("ex2.approx.ftz.f32 %0,%1;":"=f"(r):"f"(x)); return r; }
__device__ __forceinline__ float rcpa(float x){ float r; asm("rcp.approx.ftz.f32 %0,%1;":"=f"(r):"f"(x)); return r; }
__device__ __forceinline__ float fsig(float t){
    const float L2E = 1.44269504088896f;
    float e = ex2a(t * -L2E);
    float s = rcpa(1.0f + e);
    return ex2a(s * L2E);
}

__device__ __forceinline__ bool poly_ok(){
    return (__uint_as_float(g_msi) + __uint_as_float(g_msjc)) <= 1.0f;
}

__device__ __forceinline__ unsigned fkey(float f){
    unsigned u = __float_as_uint(f);
    return (u & 0x80000000u) ? ~u : (u | 0x80000000u);
}
__device__ __forceinline__ float funkey(unsigned k){
    unsigned u = (k & 0x80000000u) ? (k ^ 0x80000000u) : ~k;
    return __uint_as_float(u);
}

// ---------------- f32x2 helpers ----------------
__device__ __forceinline__ ull pk2(float x, float y){
    ull r; asm("mov.b64 %0,{%1,%2};" : "=l"(r) : "f"(x), "f"(y)); return r;
}
__device__ __forceinline__ ull fma2(ull a, ull b, ull c){
    ull d; asm("fma.rn.f32x2 %0,%1,%2,%3;" : "=l"(d) : "l"(a), "l"(b), "l"(c)); return d;
}
__device__ __forceinline__ float2 upk2(ull p){
    float2 v; asm("mov.b64 {%0,%1},%2;" : "=f"(v.x), "=f"(v.y) : "l"(p)); return v;
}

__device__ __forceinline__ float wradd(float v){
    #pragma unroll
    for (int o=16;o;o>>=1) v += __shfl_xor_sync(0xffffffffu, v, o);
    return v;
}
__device__ __forceinline__ float wrmax(float v){
    #pragma unroll
    for (int o=16;o;o>>=1) v = fmaxf(v, __shfl_xor_sync(0xffffffffu, v, o));
    return v;
}

// ---------------- kernel A: fold linear heads ----------------
__global__ void __launch_bounds__(512) kprep(
                      const float* __restrict__ W1, const float* __restrict__ W2,
                      const float* __restrict__ wt_w, const float* __restrict__ bsa,
                      const float* __restrict__ Wsa1, const float* __restrict__ Wsa2,
                      const float* __restrict__ wsat_w, const float* __restrict__ wsat_b,
                      const float* __restrict__ bsa1, const float* __restrict__ c)
{
    __shared__ float s_wt[DX], s_ws[DX], s_v2[DX], s_red[DX];
    int tid = threadIdx.x;
    int d = tid & 127, mat = tid >> 7;
    if (tid < DX){ s_wt[tid]=wt_w[tid]; s_ws[tid]=wsat_w[tid]; }
    if (tid == 0){ g_msi = 0u; g_msjc = 0u; }
    if (tid < BB) g_lmax[tid] = 0u;
    __syncthreads();
    const float* W  = (mat==0)?W1:(mat==1)?W2:(mat==2)?Wsa1:Wsa2;
    const float* vv = (mat<2)? s_wt : s_ws;
    float a = 0.f;
    #pragma unroll 4
    for (int e=0;e<DX;e++) a = fmaf(W[d*DX+e], vv[e], a);
    if      (mat==0) g_v1[d]=a;
    else if (mat==1) s_v2[d]=a;
    else if (mat==2) g_u1[d]=a;
    else             g_u2[d]=a;
    if (tid < 128) s_red[tid] = bsa[tid]*s_wt[tid];
    __syncthreads();
    for (int o=64;o;o>>=1){ if(tid<o) s_red[tid]+=s_red[tid+o]; __syncthreads(); }
    float bterm = s_red[0];
    __syncthreads();
    if (tid < 128) s_red[tid] = bsa1[tid]*s_ws[tid];
    __syncthreads();
    for (int o=64;o;o>>=1){ if(tid<o) s_red[tid]+=s_red[tid+o]; __syncthreads(); }
    if (tid==0) g_cconst = s_red[0] + wsat_b[0];
    if (tid < BB){
        float acc = bterm;
        for (int e=0;e<DX;e++) acc = fmaf(c[tid*DX+e], s_v2[e], acc);
        g_cq[tid] = acc;
    }
}

// ---------------- kernel B: per-row dots + per-batch logit max ----------------
__global__ void kdots(const float* __restrict__ x)
{
    __shared__ float smax[8];
    int gt  = blockIdx.x*blockDim.x + threadIdx.x;
    int row = gt >> 5;
    int lane = gt & 31;
    float4 xv = ((const float4*)x)[row*32 + lane];
    float4 av = ((const float4*)g_v1)[lane];
    float4 bv = ((const float4*)g_u1)[lane];
    float4 cv = ((const float4*)g_u2)[lane];
    float s0 = xv.x*av.x + xv.y*av.y + xv.z*av.z + xv.w*av.w;
    float s1 = xv.x*bv.x + xv.y*bv.y + xv.z*bv.z + xv.w*bv.w;
    float s2 = xv.x*cv.x + xv.y*cv.y + xv.z*cv.z + xv.w*cv.w;
    #pragma unroll
    for (int o=16;o;o>>=1){
        s0 += __shfl_down_sync(0xffffffffu, s0, o);
        s1 += __shfl_down_sync(0xffffffffu, s1, o);
        s2 += __shfl_down_sync(0xffffffffu, s2, o);
    }
    if (lane==0){
        float l = s0 + g_cq[row>>12];
        g_logits[row] = l;
        g_d1[row] = s1;
        g_d2[row] = s2;
        smax[threadIdx.x>>5] = l;
    }
    __syncthreads();
    if (threadIdx.x==0){
        float m = smax[0];
        #pragma unroll
        for (int w=1;w<8;w++) m = fmaxf(m, smax[w]);
        atomicMax(&g_lmax[(blockIdx.x*8)>>12], fkey(m));
    }
}

// ---------------- kernel C: partial softmax sums ----------------
__global__ void __launch_bounds__(512) kPS()
{
    int s = blockIdx.x, b = blockIdx.y, tid = threadIdx.x;
    __shared__ float sred[16];
    float m = funkey(g_lmax[b]);
    float v = __expf(g_logits[b*LL + s*512 + tid] - m);
    v = wradd(v);
    if ((tid&31)==0) sred[tid>>5] = v;
    __syncthreads();
    if (tid==0){
        float t = 0.f;
        #pragma unroll
        for (int w=0;w<16;w++) t += sred[w];
        g_psum[b*8+s] = t;
    }
}

// ---------------- kernel D: si/sjc + partial sjc-moments + ranges ----------------
__global__ void __launch_bounds__(512) kE()
{
    int s = blockIdx.x, b = blockIdx.y, tid = threadIdx.x;
    int lane = tid & 31, wid = tid >> 5;
    __shared__ float smom[16][10];
    int idx = b*LL + s*512 + tid;
    float m = funkey(g_lmax[b]);
    float t = 0.f;
    #pragma unroll
    for (int k=0;k<8;k++) t += g_psum[b*8+k];
    float inv = 1.0f/t;
    float cc = g_cconst;
    float p = __expf(g_logits[idx]-m)*inv;
    float si  = p*g_d1[idx];
    float sjc = fmaf(p, g_d2[idx], cc);
    g_si[idx]=si; g_sjc[idx]=sjc;
    float rs = wrmax(fabsf(si)), rj = wrmax(fabsf(sjc));
    if (lane==0){
        atomicMax(&g_msi,  __float_as_uint(rs));
        atomicMax(&g_msjc, __float_as_uint(rj));
    }
    float pw = 1.f;
    #pragma unroll
    for (int k=0;k<10;k++){
        float v = wradd(pw);
        if (lane==0) smom[wid][k]=v;
        pw *= sjc;
    }
    __syncthreads();
    if (tid < 10){
        float acc = 0.f;
        #pragma unroll
        for (int w=0;w<16;w++) acc += smom[w][tid];
        g_Mpart[(b*8+s)*10 + tid] = acc;
    }
}

// ---------------- kernel E: invZ + partial invZ-weighted si-moments ----------------
__global__ void __launch_bounds__(512) kZF()
{
    if (!poly_ok()) return;
    int s = blockIdx.x, b = blockIdx.y, tid = threadIdx.x;
    int lane = tid & 31, wid = tid >> 5;
    __shared__ float sE[10];
    __shared__ float smom[16][10];
    if (tid < 10){
        float M[10];
        #pragma unroll
        for (int mi=0;mi<10;mi++){
            float acc = 0.f;
            #pragma unroll
            for (int ss=0;ss<8;ss++) acc += g_Mpart[(b*8+ss)*10 + mi];
            M[mi] = acc;
        }
        float e = 0.f;
        for (int mi=0; tid+mi<10; mi++)
            e = fmaf(c_P[tid+mi]*c_BIN[tid+mi][tid], M[mi], e);
        sE[tid] = e;
    }
    __syncthreads();
    int idx = b*LL + s*512 + tid;
    float si = g_si[idx], sjc = g_sjc[idx];
    float z = sE[9];
    #pragma unroll
    for (int k=8;k>=0;k--) z = fmaf(z, si, sE[k]);
    z -= fpoly(si + sjc);
    float w = 1.0f / z;
    g_invZ[idx] = w;
    float pw = w;
    #pragma unroll
    for (int k=0;k<10;k++){
        float v = wradd(pw);
        if (lane==0) smom[wid][k]=v;
        pw *= si;
    }
    __syncthreads();
    if (tid < 10){
        float acc = 0.f;
        #pragma unroll
        for (int ww=0;ww<16;ww++) acc += smom[ww][tid];
        g_Fpart[(b*8+s)*10 + tid] = acc;
    }
}

// ============ MUFU FALLBACK (gated; 2 kernels) ============

__global__ void __launch_bounds__(256) kZfb()
{
    if (poly_ok()) return;
    __shared__ __align__(16) float ssj[1024];
    int b = blockIdx.z, jt = blockIdx.y, it = blockIdx.x;
    const float* sjc = g_sjc + b*LL + jt*1024;
    for (int j=threadIdx.x;j<1024;j+=256) ssj[j]=sjc[j];
    __syncthreads();
    int i = it*256 + threadIdx.x;
    float si = g_si[b*LL+i];
    float a0=0.f,a1=0.f,a2=0.f,a3=0.f;
    #pragma unroll 2
    for (int j=0;j<1024;j+=4){
        a0 += fsig(si+ssj[j+0]);
        a1 += fsig(si+ssj[j+1]);
        a2 += fsig(si+ssj[j+2]);
        a3 += fsig(si+ssj[j+3]);
    }
    g_Zpart[(b*4+jt)*LL + i] = (a0+a1)+(a2+a3);
}

// computes invZ in-block from Zparts, then Spart
__global__ void __launch_bounds__(256) kSfb()
{
    if (poly_ok()) return;
    __shared__ __align__(16) float ssi[1024];
    __shared__ __align__(16) float swz[1024];
    int b = blockIdx.z, ic = blockIdx.y, jt = blockIdx.x;
    int base = b*LL + ic*1024;
    for (int k=threadIdx.x;k<1024;k+=256){
        float si = g_si[base+k], sjc = g_sjc[base+k];
        float Z = 0.f;
        #pragma unroll
        for (int p=0;p<4;p++) Z += g_Zpart[(b*4+p)*LL + ic*1024 + k];
        Z -= fsig(si+sjc);
        ssi[k]=si; swz[k]=1.0f/Z;
    }
    __syncthreads();
    int j = jt*256 + threadIdx.x;
    float sj = g_sjc[b*LL+j];
    float a0=0.f,a1=0.f,a2=0.f,a3=0.f;
    #pragma unroll 2
    for (int i=0;i<1024;i+=4){
        a0 = fmaf(fsig(sj+ssi[i+0]), swz[i+0], a0);
        a1 = fmaf(fsig(sj+ssi[i+1]), swz[i+1], a1);
        a2 = fmaf(fsig(sj+ssi[i+2]), swz[i+2], a2);
        a3 = fmaf(fsig(sj+ssi[i+3]), swz[i+3], a3);
    }
    g_Spart[(b*4+ic)*LL + j] = (a0+a1)+(a2+a3);
}

// ---------------- kernel F: S -> ui -> FFN -> residual -> LayerNorm ----------------
// 64 rows/block, 128 threads (4 warps). Warp q handles cols q*32..q*32+31
// (4 tiles of 8 cols), lane = row; each lane owns rows lane and lane+32.
// Weight LDS are warp-uniform (broadcast, N=1); only x loads are lane-distinct.
// Weights staged into 32KB smem buffer one K-half at a time.
__device__ __forceinline__ void gemm_stage(const float* __restrict__ Wg,
        float* ws, const float* in_s, int lane, int qcol, int tid,
        ull acc[2][4][4])
{
    #pragma unroll
    for (int rg=0;rg<2;rg++)
        #pragma unroll
        for (int t=0;t<4;t++)
            #pragma unroll
            for (int p=0;p<4;p++) acc[rg][t][p]=0ull;

    for (int half=0; half<2; half++){
        __syncthreads();
        {   // stage 64 K-rows of weights into smem (32KB)
            const float4* src = (const float4*)(Wg + half*64*DX);
            float4* dst = (float4*)ws;
            #pragma unroll
            for (int k=0;k<16;k++) dst[tid + k*128] = src[tid + k*128];
        }
        __syncthreads();
        #pragma unroll 1
        for (int d4=0; d4<64; d4+=4){
            int dg = half*64 + d4;
            float4 xa = *(const float4*)(in_s + lane*NS + dg);
            float4 xb = *(const float4*)(in_s + (lane+32)*NS + dg);
            ull xa0=pk2(xa.x,xa.x), xa1=pk2(xa.y,xa.y), xa2=pk2(xa.z,xa.z), xa3=pk2(xa.w,xa.w);
            ull xb0=pk2(xb.x,xb.x), xb1=pk2(xb.y,xb.y), xb2=pk2(xb.z,xb.z), xb3=pk2(xb.w,xb.w);
            #pragma unroll
            for (int t=0;t<4;t++){
                const float* wp = ws + d4*DX + qcol + t*8;
                #pragma unroll
                for (int dd=0;dd<4;dd++){
                    float4 wa = *(const float4*)(wp + dd*DX);
                    float4 wb = *(const float4*)(wp + dd*DX + 4);
                    ull W0=pk2(wa.x,wa.y), W1v=pk2(wa.z,wa.w);
                    ull W2v=pk2(wb.x,wb.y), W3v=pk2(wb.z,wb.w);
                    ull xda = (dd==0)?xa0:(dd==1)?xa1:(dd==2)?xa2:xa3;
                    ull xdb = (dd==0)?xb0:(dd==1)?xb1:(dd==2)?xb2:xb3;
                    acc[0][t][0]=fma2(xda,W0 ,acc[0][t][0]);
                    acc[0][t][1]=fma2(xda,W1v,acc[0][t][1]);
                    acc[0][t][2]=fma2(xda,W2v,acc[0][t][2]);
                    acc[0][t][3]=fma2(xda,W3v,acc[0][t][3]);
                    acc[1][t][0]=fma2(xdb,W0 ,acc[1][t][0]);
                    acc[1][t][1]=fma2(xdb,W1v,acc[1][t][1]);
                    acc[1][t][2]=fma2(xdb,W2v,acc[1][t][2]);
                    acc[1][t][3]=fma2(xdb,W3v,acc[1][t][3]);
                }
            }
        }
    }
}

__global__ void __launch_bounds__(128) kffn(const float* __restrict__ x,
        const float* __restrict__ w1, const float* __restrict__ b1,
        const float* __restrict__ w2, const float* __restrict__ b2,
        const float* __restrict__ lng, const float* __restrict__ lnb,
        float* __restrict__ out)
{
    extern __shared__ float sm[];
    float* ws  = sm;                    // 8192 floats (32KB weight stage)
    float* ins = sm + 8192;             // 64*NS
    float* hs  = sm + 8192 + 64*NS;     // 64*NS
    float* sS  = sm + 8192 + 2*64*NS;   // 64
    float* sF  = sS + 64;               // 10

    int tid = threadIdx.x;
    int lane = tid & 31, q = tid >> 5;
    int qcol = q * 32;
    int rowbase = blockIdx.x * 64;
    int b = rowbase >> 12;
    bool pok = poly_ok();

    // F coefficients for this batch
    if (pok && tid < 10){
        float M[10];
        #pragma unroll
        for (int mi=0;mi<10;mi++){
            float acc = 0.f;
            #pragma unroll
            for (int ss=0;ss<8;ss++) acc += g_Fpart[(b*8+ss)*10 + mi];
            M[mi] = acc;
        }
        float e = 0.f;
        for (int mi=0; tid+mi<10; mi++)
            e = fmaf(c_P[tid+mi]*c_BIN[tid+mi][tid], M[mi], e);
        sF[tid] = e;
    }
    __syncthreads();

    // per-row S
    if (tid < 64){
        int gr = rowbase + tid;
        float s;
        if (pok){
            float sj = g_sjc[gr];
            float v = sF[9];
            #pragma unroll
            for (int k=8;k>=0;k--) v = fmaf(v, sj, sF[k]);
            s = v - fpoly(g_si[gr] + sj) * g_invZ[gr];
        } else {
            int il = gr & (LL-1);
            float fz = fsig(g_si[gr] + g_sjc[gr]);
            float Zs=0.f, Ss=0.f;
            #pragma unroll
            for (int p=0;p<4;p++){
                Zs += g_Zpart[(b*4+p)*LL+il];
                Ss += g_Spart[(b*4+p)*LL+il];
            }
            float iz = 1.0f/(Zs - fz);
            s = Ss - fz*iz;
        }
        sS[tid] = s;
    }
    __syncthreads();

    // ui = x * S
    const float4* xr = (const float4*)(x + (size_t)rowbase*DX);
    #pragma unroll
    for (int k=tid; k<2048; k+=128){
        int r = k>>5, i2 = k&31;
        float s = sS[r];
        float4 v = xr[k];
        v.x*=s; v.y*=s; v.z*=s; v.w*=s;
        *(float4*)(ins + r*NS + i2*4) = v;
    }
    // (gemm_stage starts with __syncthreads())

    ull acc[2][4][4];

    // ---- stage 1: hidden = relu(ui @ W1 + b1) ----
    gemm_stage(w1, ws, ins, lane, qcol, tid, acc);
    #pragma unroll
    for (int t=0;t<4;t++){
        int col = qcol + t*8;
        float4 bb0 = *(const float4*)(b1+col);
        float4 bb1 = *(const float4*)(b1+col+4);
        #pragma unroll
        for (int rg=0;rg<2;rg++){
            int row = lane + rg*32;
            float2 u0=upk2(acc[rg][t][0]), u1=upk2(acc[rg][t][1]);
            float2 u2=upk2(acc[rg][t][2]), u3=upk2(acc[rg][t][3]);
            float4 h0, h1;
            h0.x=fmaxf(u0.x+bb0.x,0.f); h0.y=fmaxf(u0.y+bb0.y,0.f);
            h0.z=fmaxf(u1.x+bb0.z,0.f); h0.w=fmaxf(u1.y+bb0.w,0.f);
            h1.x=fmaxf(u2.x+bb1.x,0.f); h1.y=fmaxf(u2.y+bb1.y,0.f);
            h1.z=fmaxf(u3.x+bb1.z,0.f); h1.w=fmaxf(u3.y+bb1.w,0.f);
            *(float4*)(hs + row*NS + col)     = h0;
            *(float4*)(hs + row*NS + col + 4) = h1;
        }
    }
    // (next gemm_stage's leading __syncthreads orders hs writes vs reads)

    // ---- stage 2: y = hidden @ W2 + b2 + ui ----
    gemm_stage(w2, ws, hs, lane, qcol, tid, acc);
    __syncthreads();   // everyone done reading hs before we overwrite with y
    #pragma unroll
    for (int t=0;t<4;t++){
        int col = qcol + t*8;
        float4 bb0 = *(const float4*)(b2+col);
        float4 bb1 = *(const float4*)(b2+col+4);
        #pragma unroll
        for (int rg=0;rg<2;rg++){
            int row = lane + rg*32;
            float2 u0=upk2(acc[rg][t][0]), u1=upk2(acc[rg][t][1]);
            float2 u2=upk2(acc[rg][t][2]), u3=upk2(acc[rg][t][3]);
            float4 r0 = *(const float4*)(ins + row*NS + col);
            float4 r1 = *(const float4*)(ins + row*NS + col + 4);
            float4 y0, y1;
            y0.x=u0.x+bb0.x+r0.x; y0.y=u0.y+bb0.y+r0.y;
            y0.z=u1.x+bb0.z+r0.z; y0.w=u1.y+bb0.w+r0.w;
            y1.x=u2.x+bb1.x+r1.x; y1.y=u2.y+bb1.y+r1.y;
            y1.z=u3.x+bb1.z+r1.z; y1.w=u3.y+bb1.w+r1.w;
            *(float4*)(hs + row*NS + col)     = y0;
            *(float4*)(hs + row*NS + col + 4) = y1;
        }
    }
    __syncthreads();

    // ---- LayerNorm: thread handles half a row (64 cols) ----
    {
        int row = tid >> 1, hf = tid & 1;
        const float* yb = hs + row*NS + hf*64;
        float s=0.f, ss=0.f;
        #pragma unroll
        for (int i=0;i<16;i++){
            float4 v = *(const float4*)(yb + i*4);
            s  += (v.x+v.y)+(v.z+v.w);
            ss += (v.x*v.x+v.y*v.y)+(v.z*v.z+v.w*v.w);
        }
        s  += __shfl_xor_sync(0xffffffffu, s, 1);
        ss += __shfl_xor_sync(0xffffffffu, ss, 1);
        float mu  = s * (1.0f/128.0f);
        float var = ss * (1.0f/128.0f) - mu*mu;
        float inv = rsqrtf(var + 1e-6f);
        float* ob = out + (size_t)(rowbase+row)*DX + hf*64;
        const float* gb = lng + hf*64;
        const float* be = lnb + hf*64;
        #pragma unroll
        for (int i=0;i<16;i++){
            float4 v = *(const float4*)(yb + i*4);
            float4 gg = *(const float4*)(gb + i*4);
            float4 bbv= *(const float4*)(be + i*4);
            float4 o;
            o.x = (v.x-mu)*inv*gg.x + bbv.x;
            o.y = (v.y-mu)*inv*gg.y + bbv.y;
            o.z = (v.z-mu)*inv*gg.z + bbv.z;
            o.w = (v.w-mu)*inv*gg.w + bbv.w;
            *(float4*)(ob + i*4) = o;
        }
    }
}

// ---------------- launch ----------------
extern "C" void kernel_launch(void* const* d_in, const int* in_sizes, int n_in,
                              void* d_out, int out_size)
{
    const float* x     = (const float*)d_in[0];
    const float* c     = (const float*)d_in[1];
    const float* W1    = (const float*)d_in[2];
    const float* W2    = (const float*)d_in[3];
    const float* wt_w  = (const float*)d_in[4];
    const float* bsa   = (const float*)d_in[5];
    const float* Wsa1  = (const float*)d_in[6];
    const float* Wsa2  = (const float*)d_in[7];
    const float* wsatw = (const float*)d_in[8];
    const float* wsatb = (const float*)d_in[9];
    const float* bsa1  = (const float*)d_in[10];
    const float* pw1   = (const float*)d_in[11];
    const float* pb1   = (const float*)d_in[12];
    const float* pw2   = (const float*)d_in[13];
    const float* pb2   = (const float*)d_in[14];
    const float* lng   = (const float*)d_in[15];
    const float* lnb   = (const float*)d_in[16];
    float* out = (float*)d_out;

    kprep<<<1,512>>>(W1,W2,wt_w,bsa,Wsa1,Wsa2,wsatw,wsatb,bsa1,c);
    kdots<<<(BL*32)/256,256>>>(x);
    kPS<<<dim3(8,BB),512>>>();
    kE<<<dim3(8,BB),512>>>();
    kZF<<<dim3(8,BB),512>>>();

    kZfb<<<dim3(16,4,BB),256>>>();
    kSfb<<<dim3(16,4,BB),256>>>();

    const int SMEMB = (8192 + 2*64*NS + 64 + 16) * 4;   // ~101KB
    cudaFuncSetAttribute(kffn, cudaFuncAttributeMaxDynamicSharedMemorySize, SMEMB);
    kffn<<<BL/64,128,SMEMB>>>(x,pw1,pb1,pw2,pb2,lng,lnb,out);
}

// round 7
// speedup vs baseline: 1.2732x; 1.2732x over previous
#include <cuda_runtime.h>

typedef unsigned long long ull;

#define BB 8
#define LL 4096
#define DX 128
#define BL (BB*LL)
#define NS 132      // padded smem row stride in kffn
#define GRIDN 128   // mega kernel grid (co-resident, single wave)
#define SLICES 16   // per-batch slices in mega kernel (GRIDN = BB*SLICES)
#define SLEN (LL/SLICES)   // 256 elements per slice

// ---------------- scratch ----------------
__device__ __align__(16) float g_v1[DX], g_u1[DX], g_u2[DX];
__device__ float g_cconst;
__device__ float g_logits[BL], g_d1[BL], g_d2[BL];
__device__ float g_si[BL], g_sjc[BL];
__device__ float g_invZ[BL], g_S[BL];
__device__ float g_Mpart[GRIDN*10], g_Fpart[GRIDN*10];
__device__ float g_psum[GRIDN];
__device__ unsigned g_lmax[BB];
__device__ unsigned g_msi, g_msjc;
__device__ ull g_barcnt = 0;   // monotonic grid barrier counter (never reset)

// ---------------- exp(sigmoid(t)) Taylor deg-9, valid |t|<=1 ----------------
#define P0f  1.64872127f
#define P1f  0.412180318f
#define P2f  0.0515225397f
#define P3f (-0.03005490f)
#define P4f (-0.00831874f)
#define P5f  0.00237489f
#define P6f  0.00112763f
#define P7f (-1.56355e-4f)
#define P8f (-1.38606e-4f)
#define P9f  5.4551e-6f

__constant__ float c_P[10] = {P0f,P1f,P2f,P3f,P4f,P5f,P6f,P7f,P8f,P9f};
__constant__ float c_BIN[10][10] = {
    {1,0,0,0,0,0,0,0,0,0},
    {1,1,0,0,0,0,0,0,0,0},
    {1,2,1,0,0,0,0,0,0,0},
    {1,3,3,1,0,0,0,0,0,0},
    {1,4,6,4,1,0,0,0,0,0},
    {1,5,10,10,5,1,0,0,0,0},
    {1,6,15,20,15,6,1,0,0,0},
    {1,7,21,35,35,21,7,1,0,0},
    {1,8,28,56,70,56,28,8,1,0},
    {1,9,36,84,126,126,84,36,9,1},
};

__device__ __forceinline__ float fpoly(float t){
    float r = P9f;
    r = fmaf(r,t,P8f); r = fmaf(r,t,P7f); r = fmaf(r,t,P6f);
    r = fmaf(r,t,P5f); r = fmaf(r,t,P4f); r = fmaf(r,t,P3f);
    r = fmaf(r,t,P2f); r = fmaf(r,t,P1f); r = fmaf(r,t,P0f);
    return r;
}

__device__ __forceinline__ float ex2a(float x){ float r; asm("ex2.approx.ftz.f32 %0,%1;":"=f"(r):"f"(x)); return r; }
__device__ __forceinline__ float rcpa(float x){ float r; asm("rcp.approx.ftz.f32 %0,%1;":"=f"(r):"f"(x)); return r; }
__device__ __forceinline__ float fsig(float t){
    const float L2E = 1.44269504088896f;
    float e = ex2a(t * -L2E);
    float s = rcpa(1.0f + e);
    return ex2a(s * L2E);
}

__device__ __forceinline__ bool poly_ok(){
    return (__uint_as_float(g_msi) + __uint_as_float(g_msjc)) <= 1.0f;
}

__device__ __forceinline__ unsigned fkey(float f){
    unsigned u = __float_as_uint(f);
    return (u & 0x80000000u) ? ~u : (u | 0x80000000u);
}
__device__ __forceinline__ float funkey(unsigned k){
    unsigned u = (k & 0x80000000u) ? (k ^ 0x80000000u) : ~k;
    return __uint_as_float(u);
}

// ---------------- f32x2 helpers ----------------
__device__ __forceinline__ ull pk2(float x, float y){
    ull r; asm("mov.b64 %0,{%1,%2};" : "=l"(r) : "f"(x), "f"(y)); return r;
}
__device__ __forceinline__ ull fma2(ull a, ull b, ull c){
    ull d; asm("fma.rn.f32x2 %0,%1,%2,%3;" : "=l"(d) : "l"(a), "l"(b), "l"(c)); return d;
}
__device__ __forceinline__ float2 upk2(ull p){
    float2 v; asm("mov.b64 {%0,%1},%2;" : "=f"(v.x), "=f"(v.y) : "l"(p)); return v;
}

__device__ __forceinline__ float wradd(float v){
    #pragma unroll
    for (int o=16;o;o>>=1) v += __shfl_xor_sync(0xffffffffu, v, o);
    return v;
}

// ---------------- grid barrier (monotonic ticket; all blocks co-resident) ----------------
__device__ __forceinline__ void gsync(){
    __syncthreads();
    if (threadIdx.x == 0){
        __threadfence();
        ull t = atomicAdd(&g_barcnt, 1ull);
        ull target = (t/GRIDN + 1ull) * (ull)GRIDN;
        while (*((volatile ull*)&g_barcnt) < target) __nanosleep(64);
        __threadfence();
    }
    __syncthreads();
}

// ================= MEGA KERNEL: prep -> dots -> softmax -> moments -> invZ/F =================
__global__ void __launch_bounds__(512) kmega(
        const float* __restrict__ x,
        const float* __restrict__ W1,  const float* __restrict__ wt_w,
        const float* __restrict__ Wsa1,const float* __restrict__ Wsa2,
        const float* __restrict__ wsat_w, const float* __restrict__ wsat_b,
        const float* __restrict__ bsa1)
{
    __shared__ __align__(16) float sbuf[8192];   // 32KB multi-purpose
    __shared__ float sred[16];
    __shared__ float smom[8][10];
    __shared__ float sE[10];

    int tid  = threadIdx.x;
    int lane = tid & 31, wid = tid >> 5;
    int bk = blockIdx.x;
    int b  = bk >> 4;          // batch   (SLICES=16 blocks per batch)
    int s  = bk & 15;          // slice

    // ---------- phase 0: prep (blocks 0-3) ----------
    // NOTE: c@W2 + bsa shift the logits uniformly per batch -> softmax-invariant -> dropped.
    if (bk < 3){
        float* vec = sbuf;            // 128
        float* sp  = sbuf + 128;      // 4*128
        if (tid < DX) vec[tid] = (bk==0) ? wt_w[tid] : wsat_w[tid];
        __syncthreads();
        const float* W = (bk==0)?W1:(bk==1)?Wsa1:Wsa2;
        int d = tid & 127, p = tid >> 7;
        float a = 0.f;
        #pragma unroll 8
        for (int e=p*32; e<p*32+32; e++) a = fmaf(W[d*DX+e], vec[e], a);
        sp[p*DX + d] = a;
        __syncthreads();
        if (tid < DX){
            float t = (sp[tid]+sp[DX+tid]) + (sp[2*DX+tid]+sp[3*DX+tid]);
            float* dst = (bk==0)?g_v1:(bk==1)?g_u1:g_u2;
            dst[tid] = t;
        }
    } else if (bk == 3){
        if (tid < DX) sbuf[tid] = bsa1[tid]*wsat_w[tid];
        __syncthreads();
        for (int o=64;o;o>>=1){ if(tid<o) sbuf[tid]+=sbuf[tid+o]; __syncthreads(); }
        if (tid==0){ g_cconst = sbuf[0] + wsat_b[0]; g_msi=0u; g_msjc=0u; }
        if (tid < BB) g_lmax[tid] = 0u;
    }
    gsync();

    // ---------- phase 1: per-row dots + block logit max ----------
    {
        float4 av = ((const float4*)g_v1)[lane];
        float4 bv = ((const float4*)g_u1)[lane];
        float4 cv = ((const float4*)g_u2)[lane];
        int rowbase = bk*SLEN + wid*16;
        float lmax = -1e30f;
        #pragma unroll 2
        for (int r=0;r<16;r++){
            int row = rowbase + r;
            float4 xv = ((const float4*)x)[row*32 + lane];
            float s0 = xv.x*av.x + xv.y*av.y + xv.z*av.z + xv.w*av.w;
            float s1 = xv.x*bv.x + xv.y*bv.y + xv.z*bv.z + xv.w*bv.w;
            float s2 = xv.x*cv.x + xv.y*cv.y + xv.z*cv.z + xv.w*cv.w;
            #pragma unroll
            for (int o=16;o;o>>=1){
                s0 += __shfl_down_sync(0xffffffffu, s0, o);
                s1 += __shfl_down_sync(0xffffffffu, s1, o);
                s2 += __shfl_down_sync(0xffffffffu, s2, o);
            }
            if (lane==0){
                g_logits[row]=s0; g_d1[row]=s1; g_d2[row]=s2;
                lmax = fmaxf(lmax, s0);
            }
        }
        if (lane==0) sred[wid] = lmax;
        __syncthreads();
        if (tid==0){
            float m = sred[0];
            #pragma unroll
            for (int w=1;w<16;w++) m = fmaxf(m, sred[w]);
            atomicMax(&g_lmax[b], fkey(m));
        }
    }
    gsync();

    // ---------- phase 2: partial softmax sums ----------
    {
        float m = funkey(g_lmax[b]);
        if (tid < SLEN){
            float v = __expf(g_logits[b*LL + s*SLEN + tid] - m);
            v = wradd(v);
            if (lane==0) sred[wid] = v;
        }
        __syncthreads();
        if (tid==0){
            float t = 0.f;
            #pragma unroll
            for (int w=0;w<8;w++) t += sred[w];
            g_psum[bk] = t;
        }
    }
    gsync();

    // ---------- phase 3: si/sjc + ranges + partial sjc-moments ----------
    {
        float m = funkey(g_lmax[b]);
        float t = 0.f;
        #pragma unroll
        for (int k=0;k<SLICES;k++) t += g_psum[b*SLICES+k];
        float inv = 1.0f/t;
        float cc = g_cconst;
        if (tid < SLEN){
            int idx = b*LL + s*SLEN + tid;
            float p = __expf(g_logits[idx]-m)*inv;
            float si  = p*g_d1[idx];
            float sjc = fmaf(p, g_d2[idx], cc);
            g_si[idx]=si; g_sjc[idx]=sjc;
            float rs = fabsf(si), rj = fabsf(sjc);
            #pragma unroll
            for (int o=16;o;o>>=1){
                rs = fmaxf(rs, __shfl_xor_sync(0xffffffffu, rs, o));
                rj = fmaxf(rj, __shfl_xor_sync(0xffffffffu, rj, o));
            }
            if (lane==0){
                atomicMax(&g_msi,  __float_as_uint(rs));
                atomicMax(&g_msjc, __float_as_uint(rj));
            }
            float pw = 1.f;
            #pragma unroll
            for (int k=0;k<10;k++){
                float v = wradd(pw);
                if (lane==0) smom[wid][k]=v;
                pw *= sjc;
            }
        }
        __syncthreads();
        if (tid < 10){
            float acc = 0.f;
            #pragma unroll
            for (int w=0;w<8;w++) acc += smom[w][tid];
            g_Mpart[bk*10 + tid] = acc;
        }
    }
    gsync();

    bool pok = poly_ok();   // uniform across grid (read after barrier)

    if (pok){
        // ---------- phase 4: invZ + partial invZ-weighted si-moments ----------
        if (tid < 10){
            float M[10];
            #pragma unroll
            for (int mi=0;mi<10;mi++){
                float acc = 0.f;
                #pragma unroll
                for (int ss=0;ss<SLICES;ss++) acc += g_Mpart[(b*SLICES+ss)*10 + mi];
                M[mi] = acc;
            }
            float e = 0.f;
            for (int mi=0; tid+mi<10; mi++)
                e = fmaf(c_P[tid+mi]*c_BIN[tid+mi][tid], M[mi], e);
            sE[tid] = e;
        }
        __syncthreads();
        if (tid < SLEN){
            int idx = b*LL + s*SLEN + tid;
            float si = g_si[idx], sjc = g_sjc[idx];
            float z = sE[9];
            #pragma unroll
            for (int k=8;k>=0;k--) z = fmaf(z, si, sE[k]);
            z -= fpoly(si + sjc);
            float w = 1.0f / z;
            g_invZ[idx] = w;
            float pw = w;
            #pragma unroll
            for (int k=0;k<10;k++){
                float v = wradd(pw);
                if (lane==0) smom[wid][k]=v;
                pw *= si;
            }
        }
        __syncthreads();
        if (tid < 10){
            float acc = 0.f;
            #pragma unroll
            for (int w=0;w<8;w++) acc += smom[w][tid];
            g_Fpart[bk*10 + tid] = acc;
        }
        // kernel-end implicit sync before kffn launch
    } else {
        // ---------- phase 5a (fallback): full row sums Z -> invZ ----------
        {
            for (int k=tid;k<LL;k+=512) sbuf[k] = g_sjc[b*LL+k];
            __syncthreads();
            int row = b*LL + s*SLEN + (tid>>1);
            int half = tid & 1;
            float si = g_si[row];
            float a = 0.f;
            for (int j=half*2048; j<half*2048+2048; j++) a += fsig(si + sbuf[j]);
            a += __shfl_xor_sync(0xffffffffu, a, 1);
            if (half==0){
                float Z = a - fsig(si + g_sjc[row]);
                g_invZ[row] = 1.0f / Z;
            }
        }
        gsync();
        // ---------- phase 5b (fallback): full column sums S ----------
        {
            float* s_si = sbuf;          // 4096
            float* s_wz = sbuf + 4096;   // 4096
            for (int k=tid;k<LL;k+=512){ s_si[k]=g_si[b*LL+k]; s_wz[k]=g_invZ[b*LL+k]; }
            __syncthreads();
            int col = b*LL + s*SLEN + (tid>>1);
            int half = tid & 1;
            float sj = g_sjc[col];
            float a = 0.f;
            for (int i=half*2048; i<half*2048+2048; i++)
                a = fmaf(fsig(sj + s_si[i]), s_wz[i], a);
            a += __shfl_xor_sync(0xffffffffu, a, 1);
            if (half==0)
                g_S[col] = a - fsig(g_si[col] + sj) * g_invZ[col];
        }
    }
}

// ---------------- kernel F: S -> ui -> FFN -> residual -> LayerNorm ----------------
__device__ __forceinline__ void gemm_stage(const float* __restrict__ Wg,
        float* ws, const float* in_s, int lane, int qcol, int tid,
        ull acc[2][4][4])
{
    #pragma unroll
    for (int rg=0;rg<2;rg++)
        #pragma unroll
        for (int t=0;t<4;t++)
            #pragma unroll
            for (int p=0;p<4;p++) acc[rg][t][p]=0ull;

    for (int half=0; half<2; half++){
        __syncthreads();
        {
            const float4* src = (const float4*)(Wg + half*64*DX);
            float4* dst = (float4*)ws;
            #pragma unroll
            for (int k=0;k<16;k++) dst[tid + k*128] = src[tid + k*128];
        }
        __syncthreads();
        #pragma unroll 1
        for (int d4=0; d4<64; d4+=4){
            int dg = half*64 + d4;
            float4 xa = *(const float4*)(in_s + lane*NS + dg);
            float4 xb = *(const float4*)(in_s + (lane+32)*NS + dg);
            ull xa0=pk2(xa.x,xa.x), xa1=pk2(xa.y,xa.y), xa2=pk2(xa.z,xa.z), xa3=pk2(xa.w,xa.w);
            ull xb0=pk2(xb.x,xb.x), xb1=pk2(xb.y,xb.y), xb2=pk2(xb.z,xb.z), xb3=pk2(xb.w,xb.w);
            #pragma unroll
            for (int t=0;t<4;t++){
                const float* wp = ws + d4*DX + qcol + t*8;
                #pragma unroll
                for (int dd=0;dd<4;dd++){
                    float4 wa = *(const float4*)(wp + dd*DX);
                    float4 wb = *(const float4*)(wp + dd*DX + 4);
                    ull W0=pk2(wa.x,wa.y), W1v=pk2(wa.z,wa.w);
                    ull W2v=pk2(wb.x,wb.y), W3v=pk2(wb.z,wb.w);
                    ull xda = (dd==0)?xa0:(dd==1)?xa1:(dd==2)?xa2:xa3;
                    ull xdb = (dd==0)?xb0:(dd==1)?xb1:(dd==2)?xb2:xb3;
                    acc[0][t][0]=fma2(xda,W0 ,acc[0][t][0]);
                    acc[0][t][1]=fma2(xda,W1v,acc[0][t][1]);
                    acc[0][t][2]=fma2(xda,W2v,acc[0][t][2]);
                    acc[0][t][3]=fma2(xda,W3v,acc[0][t][3]);
                    acc[1][t][0]=fma2(xdb,W0 ,acc[1][t][0]);
                    acc[1][t][1]=fma2(xdb,W1v,acc[1][t][1]);
                    acc[1][t][2]=fma2(xdb,W2v,acc[1][t][2]);
                    acc[1][t][3]=fma2(xdb,W3v,acc[1][t][3]);
                }
            }
        }
    }
}

__global__ void __launch_bounds__(128) kffn(const float* __restrict__ x,
        const float* __restrict__ w1, const float* __restrict__ b1,
        const float* __restrict__ w2, const float* __restrict__ b2,
        const float* __restrict__ lng, const float* __restrict__ lnb,
        float* __restrict__ out)
{
    extern __shared__ float sm[];
    float* ws  = sm;                    // 8192 floats (32KB weight stage)
    float* ins = sm + 8192;             // 64*NS
    float* hs  = sm + 8192 + 64*NS;     // 64*NS
    float* sS  = sm + 8192 + 2*64*NS;   // 64
    float* sF  = sS + 64;               // 10

    int tid = threadIdx.x;
    int lane = tid & 31, q = tid >> 5;
    int qcol = q * 32;
    int rowbase = blockIdx.x * 64;
    int b = rowbase >> 12;
    bool pok = poly_ok();

    if (pok && tid < 10){
        float M[10];
        #pragma unroll
        for (int mi=0;mi<10;mi++){
            float acc = 0.f;
            #pragma unroll
            for (int ss=0;ss<SLICES;ss++) acc += g_Fpart[(b*SLICES+ss)*10 + mi];
            M[mi] = acc;
        }
        float e = 0.f;
        for (int mi=0; tid+mi<10; mi++)
            e = fmaf(c_P[tid+mi]*c_BIN[tid+mi][tid], M[mi], e);
        sF[tid] = e;
    }
    __syncthreads();

    if (tid < 64){
        int gr = rowbase + tid;
        float s;
        if (pok){
            float sj = g_sjc[gr];
            float v = sF[9];
            #pragma unroll
            for (int k=8;k>=0;k--) v = fmaf(v, sj, sF[k]);
            s = v - fpoly(g_si[gr] + sj) * g_invZ[gr];
        } else {
            s = g_S[gr];
        }
        sS[tid] = s;
    }
    __syncthreads();

    const float4* xr = (const float4*)(x + (size_t)rowbase*DX);
    #pragma unroll
    for (int k=tid; k<2048; k+=128){
        int r = k>>5, i2 = k&31;
        float s = sS[r];
        float4 v = xr[k];
        v.x*=s; v.y*=s; v.z*=s; v.w*=s;
        *(float4*)(ins + r*NS + i2*4) = v;
    }

    ull acc[2][4][4];

    gemm_stage(w1, ws, ins, lane, qcol, tid, acc);
    #pragma unroll
    for (int t=0;t<4;t++){
        int col = qcol + t*8;
        float4 bb0 = *(const float4*)(b1+col);
        float4 bb1 = *(const float4*)(b1+col+4);
        #pragma unroll
        for (int rg=0;rg<2;rg++){
            int row = lane + rg*32;
            float2 u0=upk2(acc[rg][t][0]), u1=upk2(acc[rg][t][1]);
            float2 u2=upk2(acc[rg][t][2]), u3=upk2(acc[rg][t][3]);
            float4 h0, h1;
            h0.x=fmaxf(u0.x+bb0.x,0.f); h0.y=fmaxf(u0.y+bb0.y,0.f);
            h0.z=fmaxf(u1.x+bb0.z,0.f); h0.w=fmaxf(u1.y+bb0.w,0.f);
            h1.x=fmaxf(u2.x+bb1.x,0.f); h1.y=fmaxf(u2.y+bb1.y,0.f);
            h1.z=fmaxf(u3.x+bb1.z,0.f); h1.w=fmaxf(u3.y+bb1.w,0.f);
            *(float4*)(hs + row*NS + col)     = h0;
            *(float4*)(hs + row*NS + col + 4) = h1;
        }
    }

    gemm_stage(w2, ws, hs, lane, qcol, tid, acc);
    __syncthreads();
    #pragma unroll
    for (int t=0;t<4;t++){
        int col = qcol + t*8;
        float4 bb0 = *(const float4*)(b2+col);
        float4 bb1 = *(const float4*)(b2+col+4);
        #pragma unroll
        for (int rg=0;rg<2;rg++){
            int row = lane + rg*32;
            float2 u0=upk2(acc[rg][t][0]), u1=upk2(acc[rg][t][1]);
            float2 u2=upk2(acc[rg][t][2]), u3=upk2(acc[rg][t][3]);
            float4 r0 = *(const float4*)(ins + row*NS + col);
            float4 r1 = *(const float4*)(ins + row*NS + col + 4);
            float4 y0, y1;
            y0.x=u0.x+bb0.x+r0.x; y0.y=u0.y+bb0.y+r0.y;
            y0.z=u1.x+bb0.z+r0.z; y0.w=u1.y+bb0.w+r0.w;
            y1.x=u2.x+bb1.x+r1.x; y1.y=u2.y+bb1.y+r1.y;
            y1.z=u3.x+bb1.z+r1.z; y1.w=u3.y+bb1.w+r1.w;
            *(float4*)(hs + row*NS + col)     = y0;
            *(float4*)(hs + row*NS + col + 4) = y1;
        }
    }
    __syncthreads();

    {
        int row = tid >> 1, hf = tid & 1;
        const float* yb = hs + row*NS + hf*64;
        float s=0.f, ss=0.f;
        #pragma unroll
        for (int i=0;i<16;i++){
            float4 v = *(const float4*)(yb + i*4);
            s  += (v.x+v.y)+(v.z+v.w);
            ss += (v.x*v.x+v.y*v.y)+(v.z*v.z+v.w*v.w);
        }
        s  += __shfl_xor_sync(0xffffffffu, s, 1);
        ss += __shfl_xor_sync(0xffffffffu, ss, 1);
        float mu  = s * (1.0f/128.0f);
        float var = ss * (1.0f/128.0f) - mu*mu;
        float inv = rsqrtf(var + 1e-6f);
        float* ob = out + (size_t)(rowbase+row)*DX + hf*64;
        const float* gb = lng + hf*64;
        const float* be = lnb + hf*64;
        #pragma unroll
        for (int i=0;i<16;i++){
            float4 v = *(const float4*)(yb + i*4);
            float4 gg = *(const float4*)(gb + i*4);
            float4 bbv= *(const float4*)(be + i*4);
            float4 o;
            o.x = (v.x-mu)*inv*gg.x + bbv.x;
            o.y = (v.y-mu)*inv*gg.y + bbv.y;
            o.z = (v.z-mu)*inv*gg.z + bbv.z;
            o.w = (v.w-mu)*inv*gg.w + bbv.w;
            *(float4*)(ob + i*4) = o;
        }
    }
}

// ---------------- launch ----------------
extern "C" void kernel_launch(void* const* d_in, const int* in_sizes, int n_in,
                              void* d_out, int out_size)
{
    const float* x     = (const float*)d_in[0];
    const float* W1    = (const float*)d_in[2];
    const float* wt_w  = (const float*)d_in[4];
    const float* Wsa1  = (const float*)d_in[6];
    const float* Wsa2  = (const float*)d_in[7];
    const float* wsatw = (const float*)d_in[8];
    const float* wsatb = (const float*)d_in[9];
    const float* bsa1  = (const float*)d_in[10];
    const float* pw1   = (const float*)d_in[11];
    const float* pb1   = (const float*)d_in[12];
    const float* pw2   = (const float*)d_in[13];
    const float* pb2   = (const float*)d_in[14];
    const float* lng   = (const float*)d_in[15];
    const float* lnb   = (const float*)d_in[16];
    float* out = (float*)d_out;

    kmega<<<GRIDN,512>>>(x, W1, wt_w, Wsa1, Wsa2, wsatw, wsatb, bsa1);

    const int SMEMB = (8192 + 2*64*NS + 64 + 16) * 4;   // ~101KB
    cudaFuncSetAttribute(kffn, cudaFuncAttributeMaxDynamicSharedMemorySize, SMEMB);
    kffn<<<BL/64,128,SMEMB>>>(x,pw1,pb1,pw2,pb2,lng,lnb,out);
}

// round 8
// speedup vs baseline: 1.3182x; 1.0354x over previous
#include <cuda_runtime.h>

typedef unsigned long long ull;

#define BB 8
#define LL 4096
#define DX 128
#define BL (BB*LL)
#define NS 132      // padded smem row stride in kffn
#define GRIDN 128   // mega kernel grid (co-resident, single wave)
#define SLICES 16   // per-batch slices in mega kernel (GRIDN = BB*SLICES)
#define SLEN (LL/SLICES)   // 256 elements per slice

// ---------------- scratch ----------------
__device__ __align__(16) float g_v1[DX], g_u1[DX], g_u2[DX];
__device__ float g_cconst;
__device__ float g_logits[BL], g_d1[BL], g_d2[BL];
__device__ float g_si[BL], g_sjc[BL];
__device__ float g_invZ[BL], g_S[BL];
__device__ float g_Mpart[GRIDN*10], g_Fpart[GRIDN*10];
__device__ float g_psum[GRIDN];
__device__ unsigned g_lmax[BB];
__device__ unsigned g_msi, g_msjc;
__device__ ull g_barcnt = 0;   // monotonic grid barrier counter

// ---------------- exp(sigmoid(t)) Taylor deg-9, valid |t|<=1 ----------------
#define P0f  1.64872127f
#define P1f  0.412180318f
#define P2f  0.0515225397f
#define P3f (-0.03005490f)
#define P4f (-0.00831874f)
#define P5f  0.00237489f
#define P6f  0.00112763f
#define P7f (-1.56355e-4f)
#define P8f (-1.38606e-4f)
#define P9f  5.4551e-6f

__constant__ float c_P[10] = {P0f,P1f,P2f,P3f,P4f,P5f,P6f,P7f,P8f,P9f};
__constant__ float c_BIN[10][10] = {
    {1,0,0,0,0,0,0,0,0,0},
    {1,1,0,0,0,0,0,0,0,0},
    {1,2,1,0,0,0,0,0,0,0},
    {1,3,3,1,0,0,0,0,0,0},
    {1,4,6,4,1,0,0,0,0,0},
    {1,5,10,10,5,1,0,0,0,0},
    {1,6,15,20,15,6,1,0,0,0},
    {1,7,21,35,35,21,7,1,0,0},
    {1,8,28,56,70,56,28,8,1,0},
    {1,9,36,84,126,126,84,36,9,1},
};

__device__ __forceinline__ float fpoly(float t){
    float r = P9f;
    r = fmaf(r,t,P8f); r = fmaf(r,t,P7f); r = fmaf(r,t,P6f);
    r = fmaf(r,t,P5f); r = fmaf(r,t,P4f); r = fmaf(r,t,P3f);
    r = fmaf(r,t,P2f); r = fmaf(r,t,P1f); r = fmaf(r,t,P0f);
    return r;
}

__device__ __forceinline__ float ex2a(float x){ float r; asm("ex2.approx.ftz.f32 %0,%1;":"=f"(r):"f"(x)); return r; }
__device__ __forceinline__ float rcpa(float x){ float r; asm("rcp.approx.ftz.f32 %0,%1;":"=f"(r):"f"(x)); return r; }
__device__ __forceinline__ float fsig(float t){
    const float L2E = 1.44269504088896f;
    float e = ex2a(t * -L2E);
    float s = rcpa(1.0f + e);
    return ex2a(s * L2E);
}

__device__ __forceinline__ bool poly_ok(){
    return (__uint_as_float(g_msi) + __uint_as_float(g_msjc)) <= 1.0f;
}

__device__ __forceinline__ unsigned fkey(float f){
    unsigned u = __float_as_uint(f);
    return (u & 0x80000000u) ? ~u : (u | 0x80000000u);
}
__device__ __forceinline__ float funkey(unsigned k){
    unsigned u = (k & 0x80000000u) ? (k ^ 0x80000000u) : ~k;
    return __uint_as_float(u);
}

// ---------------- f32x2 helpers ----------------
__device__ __forceinline__ ull pk2(float x, float y){
    ull r; asm("mov.b64 %0,{%1,%2};" : "=l"(r) : "f"(x), "f"(y)); return r;
}
__device__ __forceinline__ ull fma2(ull a, ull b, ull c){
    ull d; asm("fma.rn.f32x2 %0,%1,%2,%3;" : "=l"(d) : "l"(a), "l"(b), "l"(c)); return d;
}
__device__ __forceinline__ float2 upk2(ull p){
    float2 v; asm("mov.b64 {%0,%1},%2;" : "=f"(v.x), "=f"(v.y) : "l"(p)); return v;
}

__device__ __forceinline__ float wradd(float v){
    #pragma unroll
    for (int o=16;o;o>>=1) v += __shfl_xor_sync(0xffffffffu, v, o);
    return v;
}

// ---------------- grid barrier ----------------
__device__ __forceinline__ void gsync(){
    __syncthreads();
    if (threadIdx.x == 0){
        __threadfence();
        ull t = atomicAdd(&g_barcnt, 1ull);
        ull target = (t/GRIDN + 1ull) * (ull)GRIDN;
        while (*((volatile ull*)&g_barcnt) < target) __nanosleep(64);
        __threadfence();
    }
    __syncthreads();
}

// ================= MEGA KERNEL =================
__global__ void __launch_bounds__(512) kmega(
        const float* __restrict__ x,
        const float* __restrict__ W1,  const float* __restrict__ wt_w,
        const float* __restrict__ Wsa1,const float* __restrict__ Wsa2,
        const float* __restrict__ wsat_w, const float* __restrict__ wsat_b,
        const float* __restrict__ bsa1)
{
    __shared__ __align__(16) float sbuf[8192];
    __shared__ float sred[16];
    __shared__ float smom[8][10];
    __shared__ float sE[10];

    int tid  = threadIdx.x;
    int lane = tid & 31, wid = tid >> 5;
    int bk = blockIdx.x;
    int b  = bk >> 4;
    int s  = bk & 15;

    // ---------- phase 0: prep ----------
    if (bk < 3){
        float* vec = sbuf;
        float* sp  = sbuf + 128;
        if (tid < DX) vec[tid] = (bk==0) ? wt_w[tid] : wsat_w[tid];
        __syncthreads();
        const float* W = (bk==0)?W1:(bk==1)?Wsa1:Wsa2;
        int d = tid & 127, p = tid >> 7;
        float a = 0.f;
        #pragma unroll 8
        for (int e=p*32; e<p*32+32; e++) a = fmaf(W[d*DX+e], vec[e], a);
        sp[p*DX + d] = a;
        __syncthreads();
        if (tid < DX){
            float t = (sp[tid]+sp[DX+tid]) + (sp[2*DX+tid]+sp[3*DX+tid]);
            float* dst = (bk==0)?g_v1:(bk==1)?g_u1:g_u2;
            dst[tid] = t;
        }
    } else if (bk == 3){
        if (tid < DX) sbuf[tid] = bsa1[tid]*wsat_w[tid];
        __syncthreads();
        for (int o=64;o;o>>=1){ if(tid<o) sbuf[tid]+=sbuf[tid+o]; __syncthreads(); }
        if (tid==0){ g_cconst = sbuf[0] + wsat_b[0]; g_msi=0u; g_msjc=0u; }
        if (tid < BB) g_lmax[tid] = 0u;
    }
    gsync();

    // ---------- phase 1: per-row dots + block logit max ----------
    {
        float4 av = ((const float4*)g_v1)[lane];
        float4 bv = ((const float4*)g_u1)[lane];
        float4 cv = ((const float4*)g_u2)[lane];
        int rowbase = bk*SLEN + wid*16;
        float lmax = -1e30f;
        #pragma unroll 2
        for (int r=0;r<16;r++){
            int row = rowbase + r;
            float4 xv = ((const float4*)x)[row*32 + lane];
            float s0 = xv.x*av.x + xv.y*av.y + xv.z*av.z + xv.w*av.w;
            float s1 = xv.x*bv.x + xv.y*bv.y + xv.z*bv.z + xv.w*bv.w;
            float s2 = xv.x*cv.x + xv.y*cv.y + xv.z*cv.z + xv.w*cv.w;
            #pragma unroll
            for (int o=16;o;o>>=1){
                s0 += __shfl_down_sync(0xffffffffu, s0, o);
                s1 += __shfl_down_sync(0xffffffffu, s1, o);
                s2 += __shfl_down_sync(0xffffffffu, s2, o);
            }
            if (lane==0){
                g_logits[row]=s0; g_d1[row]=s1; g_d2[row]=s2;
                lmax = fmaxf(lmax, s0);
            }
        }
        if (lane==0) sred[wid] = lmax;
        __syncthreads();
        if (tid==0){
            float m = sred[0];
            #pragma unroll
            for (int w=1;w<16;w++) m = fmaxf(m, sred[w]);
            atomicMax(&g_lmax[b], fkey(m));
        }
    }
    gsync();

    // ---------- phase 2: partial softmax sums ----------
    {
        float m = funkey(g_lmax[b]);
        if (tid < SLEN){
            float v = __expf(g_logits[b*LL + s*SLEN + tid] - m);
            v = wradd(v);
            if (lane==0) sred[wid] = v;
        }
        __syncthreads();
        if (tid==0){
            float t = 0.f;
            #pragma unroll
            for (int w=0;w<8;w++) t += sred[w];
            g_psum[bk] = t;
        }
    }
    gsync();

    // ---------- phase 3: si/sjc + ranges + partial sjc-moments ----------
    {
        float m = funkey(g_lmax[b]);
        float t = 0.f;
        #pragma unroll
        for (int k=0;k<SLICES;k++) t += g_psum[b*SLICES+k];
        float inv = 1.0f/t;
        float cc = g_cconst;
        if (tid < SLEN){
            int idx = b*LL + s*SLEN + tid;
            float p = __expf(g_logits[idx]-m)*inv;
            float si  = p*g_d1[idx];
            float sjc = fmaf(p, g_d2[idx], cc);
            g_si[idx]=si; g_sjc[idx]=sjc;
            float rs = fabsf(si), rj = fabsf(sjc);
            #pragma unroll
            for (int o=16;o;o>>=1){
                rs = fmaxf(rs, __shfl_xor_sync(0xffffffffu, rs, o));
                rj = fmaxf(rj, __shfl_xor_sync(0xffffffffu, rj, o));
            }
            if (lane==0){
                atomicMax(&g_msi,  __float_as_uint(rs));
                atomicMax(&g_msjc, __float_as_uint(rj));
            }
            float pw = 1.f;
            #pragma unroll
            for (int k=0;k<10;k++){
                float v = wradd(pw);
                if (lane==0) smom[wid][k]=v;
                pw *= sjc;
            }
        }
        __syncthreads();
        if (tid < 10){
            float acc = 0.f;
            #pragma unroll
            for (int w=0;w<8;w++) acc += smom[w][tid];
            g_Mpart[bk*10 + tid] = acc;
        }
    }
    gsync();

    bool pok = poly_ok();

    if (pok){
        // ---------- phase 4: invZ + partial invZ-weighted si-moments ----------
        if (tid < 10){
            float M[10];
            #pragma unroll
            for (int mi=0;mi<10;mi++){
                float acc = 0.f;
                #pragma unroll
                for (int ss=0;ss<SLICES;ss++) acc += g_Mpart[(b*SLICES+ss)*10 + mi];
                M[mi] = acc;
            }
            float e = 0.f;
            for (int mi=0; tid+mi<10; mi++)
                e = fmaf(c_P[tid+mi]*c_BIN[tid+mi][tid], M[mi], e);
            sE[tid] = e;
        }
        __syncthreads();
        if (tid < SLEN){
            int idx = b*LL + s*SLEN + tid;
            float si = g_si[idx], sjc = g_sjc[idx];
            float z = sE[9];
            #pragma unroll
            for (int k=8;k>=0;k--) z = fmaf(z, si, sE[k]);
            z -= fpoly(si + sjc);
            float w = 1.0f / z;
            g_invZ[idx] = w;
            float pw = w;
            #pragma unroll
            for (int k=0;k<10;k++){
                float v = wradd(pw);
                if (lane==0) smom[wid][k]=v;
                pw *= si;
            }
        }
        __syncthreads();
        if (tid < 10){
            float acc = 0.f;
            #pragma unroll
            for (int w=0;w<8;w++) acc += smom[w][tid];
            g_Fpart[bk*10 + tid] = acc;
        }
    } else {
        // ---------- fallback: full O(L^2) row/col sums ----------
        {
            for (int k=tid;k<LL;k+=512) sbuf[k] = g_sjc[b*LL+k];
            __syncthreads();
            int row = b*LL + s*SLEN + (tid>>1);
            int half = tid & 1;
            float si = g_si[row];
            float a = 0.f;
            for (int j=half*2048; j<half*2048+2048; j++) a += fsig(si + sbuf[j]);
            a += __shfl_xor_sync(0xffffffffu, a, 1);
            if (half==0){
                float Z = a - fsig(si + g_sjc[row]);
                g_invZ[row] = 1.0f / Z;
            }
        }
        gsync();
        {
            float* s_si = sbuf;
            float* s_wz = sbuf + 4096;
            for (int k=tid;k<LL;k+=512){ s_si[k]=g_si[b*LL+k]; s_wz[k]=g_invZ[b*LL+k]; }
            __syncthreads();
            int col = b*LL + s*SLEN + (tid>>1);
            int half = tid & 1;
            float sj = g_sjc[col];
            float a = 0.f;
            for (int i=half*2048; i<half*2048+2048; i++)
                a = fmaf(fsig(sj + s_si[i]), s_wz[i], a);
            a += __shfl_xor_sync(0xffffffffu, a, 1);
            if (half==0)
                g_S[col] = a - fsig(g_si[col] + sj) * g_invZ[col];
        }
    }
}

// ---------------- kernel F: 128 rows/block, 256 threads ----------------
// Warp q owns 16 cols (2 tiles of 8); lane owns 4 rows (lane+32*rg).
// Per warp per d4-step: 16 weight LDS.128 (uniform) + 4 x LDS.128 vs 128 fma2.
// Weights staged 32 K-rows at a time into 16KB smem buffer.
__device__ __forceinline__ void gemm_stage(const float* __restrict__ Wg,
        float* ws, const float* in_s, int lane, int qcol, int tid,
        ull acc[4][2][4])
{
    #pragma unroll
    for (int rg=0;rg<4;rg++)
        #pragma unroll
        for (int t=0;t<2;t++)
            #pragma unroll
            for (int p=0;p<4;p++) acc[rg][t][p]=0ull;

    for (int s4=0; s4<4; s4++){
        __syncthreads();
        {   // stage 32 K-rows (16KB)
            const float4* src = (const float4*)(Wg + s4*32*DX);
            float4* dst = (float4*)ws;
            #pragma unroll
            for (int k=0;k<4;k++) dst[tid + k*256] = src[tid + k*256];
        }
        __syncthreads();
        #pragma unroll 1
        for (int d4=0; d4<32; d4+=4){
            int dg = s4*32 + d4;
            ull xp[4][4];
            #pragma unroll
            for (int rg=0;rg<4;rg++){
                float4 xv = *(const float4*)(in_s + (lane+rg*32)*NS + dg);
                xp[rg][0]=pk2(xv.x,xv.x); xp[rg][1]=pk2(xv.y,xv.y);
                xp[rg][2]=pk2(xv.z,xv.z); xp[rg][3]=pk2(xv.w,xv.w);
            }
            #pragma unroll
            for (int t=0;t<2;t++){
                const float* wp = ws + d4*DX + qcol + t*8;
                #pragma unroll
                for (int dd=0;dd<4;dd++){
                    float4 wa = *(const float4*)(wp + dd*DX);
                    float4 wb = *(const float4*)(wp + dd*DX + 4);
                    ull W0=pk2(wa.x,wa.y), W1v=pk2(wa.z,wa.w);
                    ull W2v=pk2(wb.x,wb.y), W3v=pk2(wb.z,wb.w);
                    #pragma unroll
                    for (int rg=0;rg<4;rg++){
                        acc[rg][t][0]=fma2(xp[rg][dd],W0 ,acc[rg][t][0]);
                        acc[rg][t][1]=fma2(xp[rg][dd],W1v,acc[rg][t][1]);
                        acc[rg][t][2]=fma2(xp[rg][dd],W2v,acc[rg][t][2]);
                        acc[rg][t][3]=fma2(xp[rg][dd],W3v,acc[rg][t][3]);
                    }
                }
            }
        }
    }
}

__global__ void __launch_bounds__(256) kffn(const float* __restrict__ x,
        const float* __restrict__ w1, const float* __restrict__ b1,
        const float* __restrict__ w2, const float* __restrict__ b2,
        const float* __restrict__ lng, const float* __restrict__ lnb,
        float* __restrict__ out)
{
    extern __shared__ float sm[];
    float* ws  = sm;                     // 4096 floats (16KB weight stage)
    float* ins = sm + 4096;              // 128*NS
    float* hs  = sm + 4096 + 128*NS;     // 128*NS
    float* sS  = sm + 4096 + 2*128*NS;   // 128
    float* sF  = sS + 128;               // 10

    int tid = threadIdx.x;
    int lane = tid & 31, q = tid >> 5;
    int qcol = q * 16;
    int rowbase = blockIdx.x * 128;
    int b = rowbase >> 12;
    bool pok = poly_ok();

    if (pok && tid < 10){
        float M[10];
        #pragma unroll
        for (int mi=0;mi<10;mi++){
            float acc = 0.f;
            #pragma unroll
            for (int ss=0;ss<SLICES;ss++) acc += g_Fpart[(b*SLICES+ss)*10 + mi];
            M[mi] = acc;
        }
        float e = 0.f;
        for (int mi=0; tid+mi<10; mi++)
            e = fmaf(c_P[tid+mi]*c_BIN[tid+mi][tid], M[mi], e);
        sF[tid] = e;
    }
    __syncthreads();

    if (tid < 128){
        int gr = rowbase + tid;
        float s;
        if (pok){
            float sj = g_sjc[gr];
            float v = sF[9];
            #pragma unroll
            for (int k=8;k>=0;k--) v = fmaf(v, sj, sF[k]);
            s = v - fpoly(g_si[gr] + sj) * g_invZ[gr];
        } else {
            s = g_S[gr];
        }
        sS[tid] = s;
    }
    __syncthreads();

    // ui = x * S
    const float4* xr = (const float4*)(x + (size_t)rowbase*DX);
    #pragma unroll
    for (int k=tid; k<4096; k+=256){
        int r = k>>5, i2 = k&31;
        float s = sS[r];
        float4 v = xr[k];
        v.x*=s; v.y*=s; v.z*=s; v.w*=s;
        *(float4*)(ins + r*NS + i2*4) = v;
    }
    // (gemm_stage starts with __syncthreads())

    ull acc[4][2][4];

    // ---- stage 1: hidden = relu(ui @ W1 + b1) ----
    gemm_stage(w1, ws, ins, lane, qcol, tid, acc);
    #pragma unroll
    for (int t=0;t<2;t++){
        int col = qcol + t*8;
        float4 bb0 = *(const float4*)(b1+col);
        float4 bb1 = *(const float4*)(b1+col+4);
        #pragma unroll
        for (int rg=0;rg<4;rg++){
            int row = lane + rg*32;
            float2 u0=upk2(acc[rg][t][0]), u1=upk2(acc[rg][t][1]);
            float2 u2=upk2(acc[rg][t][2]), u3=upk2(acc[rg][t][3]);
            float4 h0, h1;
            h0.x=fmaxf(u0.x+bb0.x,0.f); h0.y=fmaxf(u0.y+bb0.y,0.f);
            h0.z=fmaxf(u1.x+bb0.z,0.f); h0.w=fmaxf(u1.y+bb0.w,0.f);
            h1.x=fmaxf(u2.x+bb1.x,0.f); h1.y=fmaxf(u2.y+bb1.y,0.f);
            h1.z=fmaxf(u3.x+bb1.z,0.f); h1.w=fmaxf(u3.y+bb1.w,0.f);
            *(float4*)(hs + row*NS + col)     = h0;
            *(float4*)(hs + row*NS + col + 4) = h1;
        }
    }
    // (next gemm_stage's leading __syncthreads orders hs writes vs reads)

    // ---- stage 2: y = hidden @ W2 + b2 + ui ----
    gemm_stage(w2, ws, hs, lane, qcol, tid, acc);
    __syncthreads();
    #pragma unroll
    for (int t=0;t<2;t++){
        int col = qcol + t*8;
        float4 bb0 = *(const float4*)(b2+col);
        float4 bb1 = *(const float4*)(b2+col+4);
        #pragma unroll
        for (int rg=0;rg<4;rg++){
            int row = lane + rg*32;
            float2 u0=upk2(acc[rg][t][0]), u1=upk2(acc[rg][t][1]);
            float2 u2=upk2(acc[rg][t][2]), u3=upk2(acc[rg][t][3]);
            float4 r0 = *(const float4*)(ins + row*NS + col);
            float4 r1 = *(const float4*)(ins + row*NS + col + 4);
            float4 y0, y1;
            y0.x=u0.x+bb0.x+r0.x; y0.y=u0.y+bb0.y+r0.y;
            y0.z=u1.x+bb0.z+r0.z; y0.w=u1.y+bb0.w+r0.w;
            y1.x=u2.x+bb1.x+r1.x; y1.y=u2.y+bb1.y+r1.y;
            y1.z=u3.x+bb1.z+r1.z; y1.w=u3.y+bb1.w+r1.w;
            *(float4*)(hs + row*NS + col)     = y0;
            *(float4*)(hs + row*NS + col + 4) = y1;
        }
    }
    __syncthreads();

    // ---- LayerNorm: thread handles half a row (64 cols) ----
    {
        int row = tid >> 1, hf = tid & 1;
        const float* yb = hs + row*NS + hf*64;
        float s=0.f, ss=0.f;
        #pragma unroll
        for (int i=0;i<16;i++){
            float4 v = *(const float4*)(yb + i*4);
            s  += (v.x+v.y)+(v.z+v.w);
            ss += (v.x*v.x+v.y*v.y)+(v.z*v.z+v.w*v.w);
        }
        s  += __shfl_xor_sync(0xffffffffu, s, 1);
        ss += __shfl_xor_sync(0xffffffffu, ss, 1);
        float mu  = s * (1.0f/128.0f);
        float var = ss * (1.0f/128.0f) - mu*mu;
        float inv = rsqrtf(var + 1e-6f);
        float* ob = out + (size_t)(rowbase+row)*DX + hf*64;
        const float* gb = lng + hf*64;
        const float* be = lnb + hf*64;
        #pragma unroll
        for (int i=0;i<16;i++){
            float4 v = *(const float4*)(yb + i*4);
            float4 gg = *(const float4*)(gb + i*4);
            float4 bbv= *(const float4*)(be + i*4);
            float4 o;
            o.x = (v.x-mu)*inv*gg.x + bbv.x;
            o.y = (v.y-mu)*inv*gg.y + bbv.y;
            o.z = (v.z-mu)*inv*gg.z + bbv.z;
            o.w = (v.w-mu)*inv*gg.w + bbv.w;
            *(float4*)(ob + i*4) = o;
        }
    }
}

// ---------------- launch ----------------
extern "C" void kernel_launch(void* const* d_in, const int* in_sizes, int n_in,
                              void* d_out, int out_size)
{
    const float* x     = (const float*)d_in[0];
    const float* W1    = (const float*)d_in[2];
    const float* wt_w  = (const float*)d_in[4];
    const float* Wsa1  = (const float*)d_in[6];
    const float* Wsa2  = (const float*)d_in[7];
    const float* wsatw = (const float*)d_in[8];
    const float* wsatb = (const float*)d_in[9];
    const float* bsa1  = (const float*)d_in[10];
    const float* pw1   = (const float*)d_in[11];
    const float* pb1   = (const float*)d_in[12];
    const float* pw2   = (const float*)d_in[13];
    const float* pb2   = (const float*)d_in[14];
    const float* lng   = (const float*)d_in[15];
    const float* lnb   = (const float*)d_in[16];
    float* out = (float*)d_out;

    kmega<<<GRIDN,512>>>(x, W1, wt_w, Wsa1, Wsa2, wsatw, wsatb, bsa1);

    const int SMEMB = (4096 + 2*128*NS + 128 + 16) * 4;   // ~149KB
    cudaFuncSetAttribute(kffn, cudaFuncAttributeMaxDynamicSharedMemorySize, SMEMB);
    kffn<<<BL/128,256,SMEMB>>>(x,pw1,pb1,pw2,pb2,lng,lnb,out);
}